// round 3
// baseline (speedup 1.0000x reference)
#include <cuda_runtime.h>

// SpatialTransformer: out[b,c,y,x] = bilinear_sample_zeros(src[b,c], y+flow[b,0,y,x], x+flow[b,1,y,x])
// Shapes fixed by the problem: src [8,64,256,256] f32, flow [8,2,256,256] f32, out [8,64,256,256] f32.

#define B_ 8
#define C_ 64
#define H_ 256
#define W_ 256
#define PLANE (H_ * W_)
#define CPT 8   // channels per thread

__global__ __launch_bounds__(256) void st_warp_kernel(
    const float* __restrict__ src,
    const float* __restrict__ flow,
    float* __restrict__ out)
{
    const int x  = threadIdx.x;        // 0..255
    const int y  = blockIdx.x;         // 0..255
    const int cg = blockIdx.y;         // 0..7   (channel group)
    const int b  = blockIdx.z;         // 0..7

    // ---- per-(b,y,x) prologue: flow load + bilinear weights/indices ----
    const int fbase = b * 2 * PLANE + y * W_ + x;
    const float py = (float)y + __ldg(flow + fbase);           // flow ch 0 = dy
    const float px = (float)x + __ldg(flow + fbase + PLANE);   // flow ch 1 = dx

    const float y0f = floorf(py);
    const float x0f = floorf(px);
    const float wy1 = py - y0f;
    const float wx1 = px - x0f;
    const float wy0 = 1.0f - wy1;
    const float wx0 = 1.0f - wx1;

    const int y0 = (int)y0f;
    const int x0 = (int)x0f;
    const int y1 = y0 + 1;
    const int x1 = x0 + 1;

    const bool vy0 = ((unsigned)y0 < (unsigned)H_);
    const bool vy1 = ((unsigned)y1 < (unsigned)H_);
    const bool vx0 = ((unsigned)x0 < (unsigned)W_);
    const bool vx1 = ((unsigned)x1 < (unsigned)W_);

    const float w00 = (vy0 && vx0) ? (wy0 * wx0) : 0.0f;
    const float w01 = (vy0 && vx1) ? (wy0 * wx1) : 0.0f;
    const float w10 = (vy1 && vx0) ? (wy1 * wx0) : 0.0f;
    const float w11 = (vy1 && vx1) ? (wy1 * wx1) : 0.0f;

    const int yc0 = min(max(y0, 0), H_ - 1);
    const int yc1 = min(max(y1, 0), H_ - 1);
    const int xc0 = min(max(x0, 0), W_ - 1);
    const int xc1 = min(max(x1, 0), W_ - 1);

    const int o00 = yc0 * W_ + xc0;
    const int o01 = yc0 * W_ + xc1;
    const int o10 = yc1 * W_ + xc0;
    const int o11 = yc1 * W_ + xc1;

    // ---- channel loop ----
    const int c0 = cg * CPT;
    const float* s = src + ((b * C_ + c0) * PLANE);
    float*       o = out + ((b * C_ + c0) * PLANE) + y * W_ + x;

    #pragma unroll
    for (int c = 0; c < CPT; ++c) {
        const float v00 = __ldg(s + o00);
        const float v01 = __ldg(s + o01);
        const float v10 = __ldg(s + o10);
        const float v11 = __ldg(s + o11);
        o[c * PLANE] = w00 * v00 + w01 * v01 + w10 * v10 + w11 * v11;
        s += PLANE;
    }
}

extern "C" void kernel_launch(void* const* d_in, const int* in_sizes, int n_in,
                              void* d_out, int out_size)
{
    const float* src  = (const float*)d_in[0];
    const float* flow = (const float*)d_in[1];
    float* out = (float*)d_out;

    dim3 grid(H_, C_ / CPT, B_);   // (256, 8, 8)
    dim3 block(W_);                // 256 threads, one per x
    st_warp_kernel<<<grid, block>>>(src, flow, out);
}